// round 1
// baseline (speedup 1.0000x reference)
#include <cuda_runtime.h>
#include <cuda_bf16.h>
#include <cstdint>

// Problem constants (fixed shapes per reference)
#define N_NODES 100000
#define N_EDGES 3200000
#define F0 256
#define F1 128
#define F2 64

// ---------------------------------------------------------------------------
// Scratch: __device__ globals (no allocation allowed)
// ---------------------------------------------------------------------------
__device__ int   g_cnt[N_NODES];
__device__ int   g_row_start[N_NODES + 1];
__device__ int   g_cursor[N_NODES];
__device__ int   g_ecol[N_EDGES];
__device__ float g_eval[N_EDGES];
__device__ float g_y[(size_t)N_NODES * F1];   // x @ W1
__device__ float g_h1[(size_t)N_NODES * F1];  // relu(A y + b1)
__device__ float g_z[(size_t)N_NODES * F2];   // h1 @ W2

// ---------------------------------------------------------------------------
// CSR build: zero -> histogram -> scan -> scatter
// ---------------------------------------------------------------------------
__global__ void zero_cnt_kernel() {
    int i = blockIdx.x * blockDim.x + threadIdx.x;
    int stride = gridDim.x * blockDim.x;
    for (; i < N_NODES; i += stride) g_cnt[i] = 0;
}

__global__ void hist_kernel(const int* __restrict__ rows) {
    int i = blockIdx.x * blockDim.x + threadIdx.x;
    if (i >= N_EDGES) return;
    atomicAdd(&g_cnt[rows[i]], 1);
}

// Single-CTA chunked exclusive scan over g_cnt -> g_row_start (+ cursor copy).
__global__ void scan_kernel() {
    __shared__ int sm[1024];
    const int tid = threadIdx.x;
    int carry = 0;
    for (int base = 0; base < N_NODES; base += 1024) {
        int i = base + tid;
        int v = (i < N_NODES) ? g_cnt[i] : 0;
        sm[tid] = v;
        __syncthreads();
        #pragma unroll
        for (int off = 1; off < 1024; off <<= 1) {
            int t = (tid >= off) ? sm[tid - off] : 0;
            __syncthreads();
            sm[tid] += t;
            __syncthreads();
        }
        int incl = sm[tid];
        if (i < N_NODES) {
            int ex = carry + incl - v;
            g_row_start[i] = ex;
            g_cursor[i]    = ex;
        }
        int tot = sm[1023];
        __syncthreads();
        carry += tot;
    }
    if (tid == 0) g_row_start[N_NODES] = carry;
}

__global__ void scatter_kernel(const int* __restrict__ rows,
                               const int* __restrict__ cols,
                               const float* __restrict__ vals) {
    int i = blockIdx.x * blockDim.x + threadIdx.x;
    if (i >= N_EDGES) return;
    int r = rows[i];
    int p = atomicAdd(&g_cursor[r], 1);
    g_ecol[p] = cols[i];
    g_eval[p] = vals[i];
}

// ---------------------------------------------------------------------------
// SGEMM: C[M,N] = A[M,K] @ B[K,N], fp32, smem-tiled + 8x8 register blocking
// ---------------------------------------------------------------------------
template <int BM, int BN, int BK, int TM, int TN>
__global__ void sgemm_kernel(const float* __restrict__ A,
                             const float* __restrict__ B,
                             float* __restrict__ C,
                             int M, int K, int N) {
    constexpr int THREADS = (BM / TM) * (BN / TN);
    __shared__ __align__(16) float As[BK][BM];
    __shared__ __align__(16) float Bs[BK][BN];

    const int tid = threadIdx.x;
    const int tcN = BN / TN;
    const int tr = tid / tcN;
    const int tc = tid % tcN;
    const int rowBase = blockIdx.y * BM;
    const int colBase = blockIdx.x * BN;

    constexpr int A_F4 = BM * BK / 4;
    constexpr int A_PER = A_F4 / THREADS;
    constexpr int B_F4 = BK * BN / 4;
    constexpr int B_PER = B_F4 / THREADS;
    static_assert(A_PER * THREADS == A_F4, "A load split");
    static_assert(B_PER * THREADS == B_F4, "B load split");

    float acc[TM][TN];
    #pragma unroll
    for (int i = 0; i < TM; i++)
        #pragma unroll
        for (int j = 0; j < TN; j++) acc[i][j] = 0.0f;

    for (int k0 = 0; k0 < K; k0 += BK) {
        // Load A tile (transposed into As[k][m])
        #pragma unroll
        for (int li = 0; li < A_PER; li++) {
            int f4 = tid + li * THREADS;
            int m  = f4 / (BK / 4);
            int kq = (f4 % (BK / 4)) * 4;
            int gm = rowBase + m;
            if (gm >= M) gm = M - 1;  // clamp; stores are predicated later
            float4 av = *(const float4*)(A + (size_t)gm * K + k0 + kq);
            As[kq + 0][m] = av.x;
            As[kq + 1][m] = av.y;
            As[kq + 2][m] = av.z;
            As[kq + 3][m] = av.w;
        }
        // Load B tile
        #pragma unroll
        for (int li = 0; li < B_PER; li++) {
            int f4 = tid + li * THREADS;
            int kr = f4 / (BN / 4);
            int nq = (f4 % (BN / 4)) * 4;
            *(float4*)&Bs[kr][nq] =
                *(const float4*)(B + (size_t)(k0 + kr) * N + colBase + nq);
        }
        __syncthreads();

        #pragma unroll
        for (int kk = 0; kk < BK; kk++) {
            float rm[TM], rn[TN];
            #pragma unroll
            for (int i = 0; i < TM; i += 4) {
                float4 t = *(const float4*)&As[kk][tr * TM + i];
                rm[i] = t.x; rm[i + 1] = t.y; rm[i + 2] = t.z; rm[i + 3] = t.w;
            }
            #pragma unroll
            for (int j = 0; j < TN; j += 4) {
                float4 t = *(const float4*)&Bs[kk][tc * TN + j];
                rn[j] = t.x; rn[j + 1] = t.y; rn[j + 2] = t.z; rn[j + 3] = t.w;
            }
            #pragma unroll
            for (int i = 0; i < TM; i++)
                #pragma unroll
                for (int j = 0; j < TN; j++)
                    acc[i][j] = fmaf(rm[i], rn[j], acc[i][j]);
        }
        __syncthreads();
    }

    #pragma unroll
    for (int i = 0; i < TM; i++) {
        int gm = rowBase + tr * TM + i;
        if (gm < M) {
            #pragma unroll
            for (int j = 0; j < TN; j += 4) {
                float4 o = make_float4(acc[i][j], acc[i][j + 1],
                                       acc[i][j + 2], acc[i][j + 3]);
                *(float4*)(C + (size_t)gm * N + colBase + tc * TN + j) = o;
            }
        }
    }
}

// ---------------------------------------------------------------------------
// SpMM (CSR, warp-per-row): dst[r] = op( sum_e val*src[col] + bias )
// ---------------------------------------------------------------------------
__global__ void __launch_bounds__(256)
spmm128_relu_kernel(const float* __restrict__ src,
                    const float* __restrict__ bias,
                    float* __restrict__ dst) {
    int row = blockIdx.x * 8 + threadIdx.y;
    if (row >= N_NODES) return;
    const int lane = threadIdx.x;
    const int s = g_row_start[row];
    const int e = g_row_start[row + 1];

    float4 acc = make_float4(0.f, 0.f, 0.f, 0.f);
    int j = s;
    for (; j + 32 <= e; j += 32) {
        int c   = g_ecol[j + lane];
        float v = g_eval[j + lane];
        #pragma unroll
        for (int t = 0; t < 32; t++) {
            int   cc = __shfl_sync(0xffffffffu, c, t);
            float vv = __shfl_sync(0xffffffffu, v, t);
            float4 xv = *(const float4*)(src + (size_t)cc * F1 + lane * 4);
            acc.x = fmaf(vv, xv.x, acc.x);
            acc.y = fmaf(vv, xv.y, acc.y);
            acc.z = fmaf(vv, xv.z, acc.z);
            acc.w = fmaf(vv, xv.w, acc.w);
        }
    }
    if (j < e) {
        int myj = j + lane;
        int   c = (myj < e) ? g_ecol[myj] : 0;
        float v = (myj < e) ? g_eval[myj] : 0.f;
        int cnt = e - j;
        for (int t = 0; t < cnt; t++) {
            int   cc = __shfl_sync(0xffffffffu, c, t);
            float vv = __shfl_sync(0xffffffffu, v, t);
            float4 xv = *(const float4*)(src + (size_t)cc * F1 + lane * 4);
            acc.x = fmaf(vv, xv.x, acc.x);
            acc.y = fmaf(vv, xv.y, acc.y);
            acc.z = fmaf(vv, xv.z, acc.z);
            acc.w = fmaf(vv, xv.w, acc.w);
        }
    }
    float4 b = *(const float4*)(bias + lane * 4);
    float4 o;
    o.x = fmaxf(acc.x + b.x, 0.f);
    o.y = fmaxf(acc.y + b.y, 0.f);
    o.z = fmaxf(acc.z + b.z, 0.f);
    o.w = fmaxf(acc.w + b.w, 0.f);
    *(float4*)(dst + (size_t)row * F1 + lane * 4) = o;
}

__global__ void __launch_bounds__(256)
spmm64_bias_kernel(const float* __restrict__ src,
                   const float* __restrict__ bias,
                   float* __restrict__ dst) {
    int row = blockIdx.x * 8 + threadIdx.y;
    if (row >= N_NODES) return;
    const int lane = threadIdx.x;
    const int s = g_row_start[row];
    const int e = g_row_start[row + 1];

    float2 acc = make_float2(0.f, 0.f);
    int j = s;
    for (; j + 32 <= e; j += 32) {
        int c   = g_ecol[j + lane];
        float v = g_eval[j + lane];
        #pragma unroll
        for (int t = 0; t < 32; t++) {
            int   cc = __shfl_sync(0xffffffffu, c, t);
            float vv = __shfl_sync(0xffffffffu, v, t);
            float2 xv = *(const float2*)(src + (size_t)cc * F2 + lane * 2);
            acc.x = fmaf(vv, xv.x, acc.x);
            acc.y = fmaf(vv, xv.y, acc.y);
        }
    }
    if (j < e) {
        int myj = j + lane;
        int   c = (myj < e) ? g_ecol[myj] : 0;
        float v = (myj < e) ? g_eval[myj] : 0.f;
        int cnt = e - j;
        for (int t = 0; t < cnt; t++) {
            int   cc = __shfl_sync(0xffffffffu, c, t);
            float vv = __shfl_sync(0xffffffffu, v, t);
            float2 xv = *(const float2*)(src + (size_t)cc * F2 + lane * 2);
            acc.x = fmaf(vv, xv.x, acc.x);
            acc.y = fmaf(vv, xv.y, acc.y);
        }
    }
    float2 b = *(const float2*)(bias + lane * 2);
    float2 o;
    o.x = acc.x + b.x;
    o.y = acc.y + b.y;
    *(float2*)(dst + (size_t)row * F2 + lane * 2) = o;
}

// ---------------------------------------------------------------------------
// Launch: CSR build -> y = x@W1 -> h1 = relu(A y + b1) -> z = h1@W2
//         -> out = A z + b2
// (reassociation: (A x) W = A (x W), exact in real arithmetic)
// ---------------------------------------------------------------------------
extern "C" void kernel_launch(void* const* d_in, const int* in_sizes, int n_in,
                              void* d_out, int out_size) {
    const float* x    = (const float*)d_in[0];
    const int*   rows = (const int*)d_in[1];
    const int*   cols = (const int*)d_in[2];
    const float* vals = (const float*)d_in[3];
    const float* W1   = (const float*)d_in[4];
    const float* b1   = (const float*)d_in[5];
    const float* W2   = (const float*)d_in[6];
    const float* b2   = (const float*)d_in[7];
    float* out = (float*)d_out;

    void *yp, *h1p, *zp;
    cudaGetSymbolAddress(&yp,  g_y);
    cudaGetSymbolAddress(&h1p, g_h1);
    cudaGetSymbolAddress(&zp,  g_z);
    float* y  = (float*)yp;
    float* h1 = (float*)h1p;
    float* z  = (float*)zp;

    // CSR build (deterministic up to within-row edge order; sums invariant to
    // edge set, only fp rounding order differs — well within 1e-3)
    zero_cnt_kernel<<<400, 256>>>();
    hist_kernel<<<(N_EDGES + 255) / 256, 256>>>(rows);
    scan_kernel<<<1, 1024>>>();
    scatter_kernel<<<(N_EDGES + 255) / 256, 256>>>(rows, cols, vals);

    // y = x @ W1   [100000,256] x [256,128]
    {
        dim3 grid(F1 / 128, (N_NODES + 127) / 128);
        sgemm_kernel<128, 128, 8, 8, 8><<<grid, 256>>>(x, W1, y,
                                                       N_NODES, F0, F1);
    }
    // h1 = relu(A y + b1)
    spmm128_relu_kernel<<<(N_NODES + 7) / 8, dim3(32, 8)>>>(y, b1, h1);

    // z = h1 @ W2  [100000,128] x [128,64]
    {
        dim3 grid(F2 / 64, (N_NODES + 127) / 128);
        sgemm_kernel<128, 64, 8, 8, 8><<<grid, 128>>>(h1, W2, z,
                                                      N_NODES, F1, F2);
    }
    // out = A z + b2
    spmm64_bias_kernel<<<(N_NODES + 7) / 8, dim3(32, 8)>>>(z, b2, out);
}

// round 2
// speedup vs baseline: 1.1700x; 1.1700x over previous
#include <cuda_runtime.h>
#include <cuda_bf16.h>
#include <cstdint>

// Problem constants (fixed shapes per reference)
#define N_NODES 100000
#define N_EDGES 3200000
#define F0 256
#define F1 128
#define F2 64
#define N_CHUNKS ((N_NODES + 1023) / 1024)   // 98

// ---------------------------------------------------------------------------
// Scratch: __device__ globals (no allocation allowed)
// ---------------------------------------------------------------------------
__device__ int                g_cnt[N_NODES];
__device__ int                g_row_start[N_NODES + 1];
__device__ int                g_cursor[N_NODES];
__device__ int                g_part[128];
__device__ unsigned long long g_edge[N_EDGES];              // (val<<32)|col packed
__device__ float              g_y[(size_t)N_NODES * F1];    // x @ W1
__device__ float              g_h1[(size_t)N_NODES * F1];   // relu(A y + b1)
__device__ float              g_z[(size_t)N_NODES * F2];    // h1 @ W2

// ---------------------------------------------------------------------------
// Packed f32x2 FMA (FFMA2) — ptxas never emits this from C++; PTX-only.
// ---------------------------------------------------------------------------
__device__ __forceinline__ void ffma2(unsigned long long& d,
                                      unsigned long long a,
                                      unsigned long long b) {
    asm("fma.rn.f32x2 %0, %1, %2, %0;" : "+l"(d) : "l"(a), "l"(b));
}

union F4U2 {
    float4 f;
    unsigned long long u[2];
    float  s[4];
};

// ---------------------------------------------------------------------------
// CSR build: zero -> histogram -> 3-phase scan -> scatter (packed records)
// ---------------------------------------------------------------------------
__global__ void zero_cnt_kernel() {
    int i = blockIdx.x * blockDim.x + threadIdx.x;
    int stride = gridDim.x * blockDim.x;
    for (; i < N_NODES; i += stride) g_cnt[i] = 0;
}

__global__ void hist_kernel(const int* __restrict__ rows) {
    int i = blockIdx.x * blockDim.x + threadIdx.x;
    if (i >= N_EDGES) return;
    atomicAdd(&g_cnt[rows[i]], 1);
}

// Phase 1: per-1024-chunk block scan; local exclusive -> g_row_start, chunk
// total -> g_part[chunk].
__global__ void scan1_kernel() {
    __shared__ int sm[1024];
    const int tid = threadIdx.x;
    const int i = blockIdx.x * 1024 + tid;
    int v = (i < N_NODES) ? g_cnt[i] : 0;
    sm[tid] = v;
    __syncthreads();
    #pragma unroll
    for (int off = 1; off < 1024; off <<= 1) {
        int t = (tid >= off) ? sm[tid - off] : 0;
        __syncthreads();
        sm[tid] += t;
        __syncthreads();
    }
    if (i < N_NODES) g_row_start[i] = sm[tid] - v;   // local exclusive
    if (tid == 1023) g_part[blockIdx.x] = sm[1023];  // chunk total
}

// Phase 2: exclusive scan of the 98 chunk totals, plus grand total.
__global__ void scan2_kernel() {
    __shared__ int sm[128];
    const int tid = threadIdx.x;
    int v = (tid < N_CHUNKS) ? g_part[tid] : 0;
    sm[tid] = v;
    __syncthreads();
    #pragma unroll
    for (int off = 1; off < 128; off <<= 1) {
        int t = (tid >= off) ? sm[tid - off] : 0;
        __syncthreads();
        sm[tid] += t;
        __syncthreads();
    }
    if (tid < N_CHUNKS) g_part[tid] = sm[tid] - v;
    if (tid == 127) g_row_start[N_NODES] = sm[127];
}

// Phase 3: add chunk offsets; initialize cursors.
__global__ void scan3_kernel() {
    const int i = blockIdx.x * 1024 + threadIdx.x;
    if (i >= N_NODES) return;
    int r = g_row_start[i] + g_part[blockIdx.x];
    g_row_start[i] = r;
    g_cursor[i]    = r;
}

__global__ void scatter_kernel(const int* __restrict__ rows,
                               const int* __restrict__ cols,
                               const float* __restrict__ vals) {
    int i = blockIdx.x * blockDim.x + threadIdx.x;
    if (i >= N_EDGES) return;
    int r = rows[i];
    unsigned long long pk =
        ((unsigned long long)__float_as_uint(vals[i]) << 32) |
        (unsigned int)cols[i];
    int p = atomicAdd(&g_cursor[r], 1);
    g_edge[p] = pk;   // one random 8B store instead of two 4B stores
}

// ---------------------------------------------------------------------------
// SGEMM: C[M,N] = A[M,K] @ B[K,N], fp32, smem-tiled, 8x8 regs, FFMA2 core.
// A is stored DUPLICATED in smem ((a,a) float2 per element) so the inner loop
// reads ready-made f32x2 broadcast pairs with plain LDS.128 — no packing.
// ---------------------------------------------------------------------------
template <int BM, int BN, int BK, int TM, int TN>
__global__ void sgemm_kernel(const float* __restrict__ A,
                             const float* __restrict__ B,
                             float* __restrict__ C,
                             int M, int K, int N) {
    constexpr int THREADS = (BM / TM) * (BN / TN);
    __shared__ __align__(16) float2 As2[BK][BM];   // duplicated A
    __shared__ __align__(16) float  Bs[BK][BN];

    const int tid = threadIdx.x;
    const int tcN = BN / TN;
    const int tr = tid / tcN;
    const int tc = tid % tcN;
    const int rowBase = blockIdx.y * BM;
    const int colBase = blockIdx.x * BN;

    constexpr int A_F4 = BM * BK / 4;
    constexpr int A_PER = A_F4 / THREADS;
    constexpr int B_F4 = BK * BN / 4;
    constexpr int B_PER = B_F4 / THREADS;
    static_assert(A_PER * THREADS == A_F4, "A load split");
    static_assert(B_PER * THREADS == B_F4, "B load split");

    unsigned long long acc2[TM][TN / 2];
    #pragma unroll
    for (int i = 0; i < TM; i++)
        #pragma unroll
        for (int j = 0; j < TN / 2; j++) acc2[i][j] = 0ull;

    for (int k0 = 0; k0 < K; k0 += BK) {
        // Load A tile: duplicate each value into a float2 at As2[k][m]
        #pragma unroll
        for (int li = 0; li < A_PER; li++) {
            int f4 = tid + li * THREADS;
            int m  = f4 / (BK / 4);
            int kq = (f4 % (BK / 4)) * 4;
            int gm = rowBase + m;
            if (gm >= M) gm = M - 1;  // clamp; stores predicated later
            float4 av = *(const float4*)(A + (size_t)gm * K + k0 + kq);
            As2[kq + 0][m] = make_float2(av.x, av.x);
            As2[kq + 1][m] = make_float2(av.y, av.y);
            As2[kq + 2][m] = make_float2(av.z, av.z);
            As2[kq + 3][m] = make_float2(av.w, av.w);
        }
        // Load B tile
        #pragma unroll
        for (int li = 0; li < B_PER; li++) {
            int f4 = tid + li * THREADS;
            int kr = f4 / (BN / 4);
            int nq = (f4 % (BN / 4)) * 4;
            *(float4*)&Bs[kr][nq] =
                *(const float4*)(B + (size_t)(k0 + kr) * N + colBase + nq);
        }
        __syncthreads();

        #pragma unroll
        for (int kk = 0; kk < BK; kk++) {
            unsigned long long a2[TM];
            #pragma unroll
            for (int i = 0; i < TM; i += 2) {
                F4U2 t;
                t.f = *(const float4*)&As2[kk][tr * TM + i];
                a2[i]     = t.u[0];   // (a_i, a_i)
                a2[i + 1] = t.u[1];   // (a_{i+1}, a_{i+1})
            }
            unsigned long long b2[TN / 2];
            #pragma unroll
            for (int j = 0; j < TN; j += 4) {
                F4U2 t;
                t.f = *(const float4*)&Bs[kk][tc * TN + j];
                b2[j / 2]     = t.u[0];   // (b_j, b_{j+1})
                b2[j / 2 + 1] = t.u[1];   // (b_{j+2}, b_{j+3})
            }
            #pragma unroll
            for (int i = 0; i < TM; i++)
                #pragma unroll
                for (int j = 0; j < TN / 2; j++)
                    ffma2(acc2[i][j], a2[i], b2[j]);
        }
        __syncthreads();
    }

    #pragma unroll
    for (int i = 0; i < TM; i++) {
        int gm = rowBase + tr * TM + i;
        if (gm < M) {
            #pragma unroll
            for (int j = 0; j < TN / 2; j += 2) {
                F4U2 o;
                o.u[0] = acc2[i][j];
                o.u[1] = acc2[i][j + 1];
                *(float4*)(C + (size_t)gm * N + colBase + tc * TN + 2 * j) = o.f;
            }
        }
    }
}

// ---------------------------------------------------------------------------
// SpMM (CSR, warp-per-row): dst[r] = op( sum_e val*src[col] + bias )
// ---------------------------------------------------------------------------
__global__ void __launch_bounds__(256)
spmm128_relu_kernel(const float* __restrict__ src,
                    const float* __restrict__ bias,
                    float* __restrict__ dst) {
    int row = blockIdx.x * 8 + threadIdx.y;
    if (row >= N_NODES) return;
    const int lane = threadIdx.x;
    const int s = g_row_start[row];
    const int e = g_row_start[row + 1];

    float4 acc = make_float4(0.f, 0.f, 0.f, 0.f);
    int j = s;
    for (; j + 32 <= e; j += 32) {
        unsigned long long pe = g_edge[j + lane];
        int   c = (int)(unsigned int)pe;
        float v = __uint_as_float((unsigned int)(pe >> 32));
        #pragma unroll
        for (int t = 0; t < 32; t++) {
            int   cc = __shfl_sync(0xffffffffu, c, t);
            float vv = __shfl_sync(0xffffffffu, v, t);
            float4 xv = *(const float4*)(src + (size_t)cc * F1 + lane * 4);
            acc.x = fmaf(vv, xv.x, acc.x);
            acc.y = fmaf(vv, xv.y, acc.y);
            acc.z = fmaf(vv, xv.z, acc.z);
            acc.w = fmaf(vv, xv.w, acc.w);
        }
    }
    if (j < e) {
        int myj = j + lane;
        unsigned long long pe = (myj < e) ? g_edge[myj] : 0ull;
        int   c = (int)(unsigned int)pe;
        float v = __uint_as_float((unsigned int)(pe >> 32));
        int cnt = e - j;
        for (int t = 0; t < cnt; t++) {
            int   cc = __shfl_sync(0xffffffffu, c, t);
            float vv = __shfl_sync(0xffffffffu, v, t);
            float4 xv = *(const float4*)(src + (size_t)cc * F1 + lane * 4);
            acc.x = fmaf(vv, xv.x, acc.x);
            acc.y = fmaf(vv, xv.y, acc.y);
            acc.z = fmaf(vv, xv.z, acc.z);
            acc.w = fmaf(vv, xv.w, acc.w);
        }
    }
    float4 b = *(const float4*)(bias + lane * 4);
    float4 o;
    o.x = fmaxf(acc.x + b.x, 0.f);
    o.y = fmaxf(acc.y + b.y, 0.f);
    o.z = fmaxf(acc.z + b.z, 0.f);
    o.w = fmaxf(acc.w + b.w, 0.f);
    *(float4*)(dst + (size_t)row * F1 + lane * 4) = o;
}

__global__ void __launch_bounds__(256)
spmm64_bias_kernel(const float* __restrict__ src,
                   const float* __restrict__ bias,
                   float* __restrict__ dst) {
    int row = blockIdx.x * 8 + threadIdx.y;
    if (row >= N_NODES) return;
    const int lane = threadIdx.x;
    const int s = g_row_start[row];
    const int e = g_row_start[row + 1];

    float2 acc = make_float2(0.f, 0.f);
    int j = s;
    for (; j + 32 <= e; j += 32) {
        unsigned long long pe = g_edge[j + lane];
        int   c = (int)(unsigned int)pe;
        float v = __uint_as_float((unsigned int)(pe >> 32));
        #pragma unroll
        for (int t = 0; t < 32; t++) {
            int   cc = __shfl_sync(0xffffffffu, c, t);
            float vv = __shfl_sync(0xffffffffu, v, t);
            float2 xv = *(const float2*)(src + (size_t)cc * F2 + lane * 2);
            acc.x = fmaf(vv, xv.x, acc.x);
            acc.y = fmaf(vv, xv.y, acc.y);
        }
    }
    if (j < e) {
        int myj = j + lane;
        unsigned long long pe = (myj < e) ? g_edge[myj] : 0ull;
        int   c = (int)(unsigned int)pe;
        float v = __uint_as_float((unsigned int)(pe >> 32));
        int cnt = e - j;
        for (int t = 0; t < cnt; t++) {
            int   cc = __shfl_sync(0xffffffffu, c, t);
            float vv = __shfl_sync(0xffffffffu, v, t);
            float2 xv = *(const float2*)(src + (size_t)cc * F2 + lane * 2);
            acc.x = fmaf(vv, xv.x, acc.x);
            acc.y = fmaf(vv, xv.y, acc.y);
        }
    }
    float2 b = *(const float2*)(bias + lane * 2);
    float2 o;
    o.x = acc.x + b.x;
    o.y = acc.y + b.y;
    *(float2*)(dst + (size_t)row * F2 + lane * 2) = o;
}

// ---------------------------------------------------------------------------
// Launch: CSR build -> y = x@W1 -> h1 = relu(A y + b1) -> z = h1@W2
//         -> out = A z + b2
// (reassociation: (A x) W = A (x W), exact in real arithmetic)
// ---------------------------------------------------------------------------
extern "C" void kernel_launch(void* const* d_in, const int* in_sizes, int n_in,
                              void* d_out, int out_size) {
    const float* x    = (const float*)d_in[0];
    const int*   rows = (const int*)d_in[1];
    const int*   cols = (const int*)d_in[2];
    const float* vals = (const float*)d_in[3];
    const float* W1   = (const float*)d_in[4];
    const float* b1   = (const float*)d_in[5];
    const float* W2   = (const float*)d_in[6];
    const float* b2   = (const float*)d_in[7];
    float* out = (float*)d_out;

    void *yp, *h1p, *zp;
    cudaGetSymbolAddress(&yp,  g_y);
    cudaGetSymbolAddress(&h1p, g_h1);
    cudaGetSymbolAddress(&zp,  g_z);
    float* y  = (float*)yp;
    float* h1 = (float*)h1p;
    float* z  = (float*)zp;

    // CSR build
    zero_cnt_kernel<<<400, 256>>>();
    hist_kernel<<<(N_EDGES + 255) / 256, 256>>>(rows);
    scan1_kernel<<<N_CHUNKS, 1024>>>();
    scan2_kernel<<<1, 128>>>();
    scan3_kernel<<<N_CHUNKS, 1024>>>();
    scatter_kernel<<<(N_EDGES + 255) / 256, 256>>>(rows, cols, vals);

    // y = x @ W1   [100000,256] x [256,128]
    {
        dim3 grid(F1 / 128, (N_NODES + 127) / 128);
        sgemm_kernel<128, 128, 16, 8, 8><<<grid, 256>>>(x, W1, y,
                                                        N_NODES, F0, F1);
    }
    // h1 = relu(A y + b1)
    spmm128_relu_kernel<<<(N_NODES + 7) / 8, dim3(32, 8)>>>(y, b1, h1);

    // z = h1 @ W2  [100000,128] x [128,64]
    {
        dim3 grid(F2 / 64, (N_NODES + 127) / 128);
        sgemm_kernel<128, 64, 16, 8, 8><<<grid, 128>>>(h1, W2, z,
                                                       N_NODES, F1, F2);
    }
    // out = A z + b2
    spmm64_bias_kernel<<<(N_NODES + 7) / 8, dim3(32, 8)>>>(z, b2, out);
}

// round 3
// speedup vs baseline: 1.3122x; 1.1215x over previous
#include <cuda_runtime.h>
#include <cuda_fp16.h>
#include <cuda_bf16.h>
#include <cstdint>

// Problem constants (fixed shapes per reference)
#define N_NODES 100000
#define N_EDGES 3200000
#define F0 256
#define F1 128
#define F2 64
#define N_CHUNKS ((N_NODES + 1023) / 1024)   // 98

// ---------------------------------------------------------------------------
// Scratch: __device__ globals (no allocation allowed)
// ---------------------------------------------------------------------------
__device__ int                g_cnt[N_NODES];
__device__ int                g_row_start[N_NODES + 1];
__device__ int                g_cursor[N_NODES];
__device__ int                g_part[128];
__device__ unsigned long long g_edge[N_EDGES];                  // (val<<32)|col
__device__ __half2            g_y[(size_t)N_NODES * F1 / 2];    // x @ W1  (fp16)
__device__ float              g_h1[(size_t)N_NODES * F1];       // relu(A y + b1)
__device__ __half2            g_z[(size_t)N_NODES * F2 / 2];    // h1 @ W2 (fp16)

// ---------------------------------------------------------------------------
// Packed f32x2 FMA (FFMA2) — ptxas never emits this from C++; PTX-only.
// ---------------------------------------------------------------------------
__device__ __forceinline__ void ffma2(unsigned long long& d,
                                      unsigned long long a,
                                      unsigned long long b) {
    asm("fma.rn.f32x2 %0, %1, %2, %0;" : "+l"(d) : "l"(a), "l"(b));
}

union F4U2 {
    float4 f;
    unsigned long long u[2];
    float  s[4];
};

// ---------------------------------------------------------------------------
// CSR build: zero -> histogram -> 3-phase scan -> scatter (packed records)
// ---------------------------------------------------------------------------
__global__ void zero_cnt_kernel() {
    int i = blockIdx.x * blockDim.x + threadIdx.x;
    int stride = gridDim.x * blockDim.x;
    for (; i < N_NODES; i += stride) g_cnt[i] = 0;
}

__global__ void hist_kernel(const int* __restrict__ rows) {
    int i = blockIdx.x * blockDim.x + threadIdx.x;
    if (i >= N_EDGES) return;
    atomicAdd(&g_cnt[rows[i]], 1);
}

__global__ void scan1_kernel() {
    __shared__ int sm[1024];
    const int tid = threadIdx.x;
    const int i = blockIdx.x * 1024 + tid;
    int v = (i < N_NODES) ? g_cnt[i] : 0;
    sm[tid] = v;
    __syncthreads();
    #pragma unroll
    for (int off = 1; off < 1024; off <<= 1) {
        int t = (tid >= off) ? sm[tid - off] : 0;
        __syncthreads();
        sm[tid] += t;
        __syncthreads();
    }
    if (i < N_NODES) g_row_start[i] = sm[tid] - v;
    if (tid == 1023) g_part[blockIdx.x] = sm[1023];
}

__global__ void scan2_kernel() {
    __shared__ int sm[128];
    const int tid = threadIdx.x;
    int v = (tid < N_CHUNKS) ? g_part[tid] : 0;
    sm[tid] = v;
    __syncthreads();
    #pragma unroll
    for (int off = 1; off < 128; off <<= 1) {
        int t = (tid >= off) ? sm[tid - off] : 0;
        __syncthreads();
        sm[tid] += t;
        __syncthreads();
    }
    if (tid < N_CHUNKS) g_part[tid] = sm[tid] - v;
    if (tid == 127) g_row_start[N_NODES] = sm[127];
}

__global__ void scan3_kernel() {
    const int i = blockIdx.x * 1024 + threadIdx.x;
    if (i >= N_NODES) return;
    int r = g_row_start[i] + g_part[blockIdx.x];
    g_row_start[i] = r;
    g_cursor[i]    = r;
}

__global__ void scatter_kernel(const int* __restrict__ rows,
                               const int* __restrict__ cols,
                               const float* __restrict__ vals) {
    int i = blockIdx.x * blockDim.x + threadIdx.x;
    if (i >= N_EDGES) return;
    int r = rows[i];
    unsigned long long pk =
        ((unsigned long long)__float_as_uint(vals[i]) << 32) |
        (unsigned int)cols[i];
    int p = atomicAdd(&g_cursor[r], 1);
    g_edge[p] = pk;
}

// ---------------------------------------------------------------------------
// SGEMM: C = A @ B, fp32 math, FFMA2 core, register-prefetch pipelining.
// OUT_HALF: epilogue converts to fp16 (for SpMM gather operands).
// ---------------------------------------------------------------------------
template <int BM, int BN, int BK, int TM, int TN, bool OUT_HALF>
__global__ void sgemm_kernel(const float* __restrict__ A,
                             const float* __restrict__ B,
                             void* __restrict__ Cv,
                             int M, int K, int N) {
    constexpr int THREADS = (BM / TM) * (BN / TN);
    __shared__ __align__(16) float2 As2[BK][BM];   // duplicated A: (a,a)
    __shared__ __align__(16) float  Bs[BK][BN];

    const int tid = threadIdx.x;
    const int tcN = BN / TN;
    const int tr = tid / tcN;
    const int tc = tid % tcN;
    const int rowBase = blockIdx.y * BM;
    const int colBase = blockIdx.x * BN;

    constexpr int A_F4 = BM * BK / 4;
    constexpr int A_PER = A_F4 / THREADS;
    constexpr int B_F4 = BK * BN / 4;
    constexpr int B_PER = B_F4 / THREADS;
    static_assert(A_PER * THREADS == A_F4, "A load split");
    static_assert(B_PER * THREADS == B_F4, "B load split");

    unsigned long long acc2[TM][TN / 2];
    #pragma unroll
    for (int i = 0; i < TM; i++)
        #pragma unroll
        for (int j = 0; j < TN / 2; j++) acc2[i][j] = 0ull;

    float4 pa[A_PER], pb[B_PER];

    auto load_tile = [&](int k0) {
        #pragma unroll
        for (int li = 0; li < A_PER; li++) {
            int f4 = tid + li * THREADS;
            int m  = f4 / (BK / 4);
            int kq = (f4 % (BK / 4)) * 4;
            int gm = rowBase + m;
            if (gm >= M) gm = M - 1;  // clamp; stores predicated later
            pa[li] = *(const float4*)(A + (size_t)gm * K + k0 + kq);
        }
        #pragma unroll
        for (int li = 0; li < B_PER; li++) {
            int f4 = tid + li * THREADS;
            int kr = f4 / (BN / 4);
            int nq = (f4 % (BN / 4)) * 4;
            pb[li] = *(const float4*)(B + (size_t)(k0 + kr) * N + colBase + nq);
        }
    };

    load_tile(0);

    for (int k0 = 0; k0 < K; k0 += BK) {
        // Commit prefetched tile to smem
        #pragma unroll
        for (int li = 0; li < A_PER; li++) {
            int f4 = tid + li * THREADS;
            int m  = f4 / (BK / 4);
            int kq = (f4 % (BK / 4)) * 4;
            As2[kq + 0][m] = make_float2(pa[li].x, pa[li].x);
            As2[kq + 1][m] = make_float2(pa[li].y, pa[li].y);
            As2[kq + 2][m] = make_float2(pa[li].z, pa[li].z);
            As2[kq + 3][m] = make_float2(pa[li].w, pa[li].w);
        }
        #pragma unroll
        for (int li = 0; li < B_PER; li++) {
            int f4 = tid + li * THREADS;
            int kr = f4 / (BN / 4);
            int nq = (f4 % (BN / 4)) * 4;
            *(float4*)&Bs[kr][nq] = pb[li];
        }
        __syncthreads();

        if (k0 + BK < K) load_tile(k0 + BK);   // overlap with compute

        #pragma unroll
        for (int kk = 0; kk < BK; kk++) {
            unsigned long long a2[TM];
            #pragma unroll
            for (int i = 0; i < TM; i += 2) {
                F4U2 t;
                t.f = *(const float4*)&As2[kk][tr * TM + i];
                a2[i]     = t.u[0];
                a2[i + 1] = t.u[1];
            }
            unsigned long long b2[TN / 2];
            #pragma unroll
            for (int j = 0; j < TN; j += 4) {
                F4U2 t;
                t.f = *(const float4*)&Bs[kk][tc * TN + j];
                b2[j / 2]     = t.u[0];
                b2[j / 2 + 1] = t.u[1];
            }
            #pragma unroll
            for (int i = 0; i < TM; i++)
                #pragma unroll
                for (int j = 0; j < TN / 2; j++)
                    ffma2(acc2[i][j], a2[i], b2[j]);
        }
        __syncthreads();
    }

    #pragma unroll
    for (int i = 0; i < TM; i++) {
        int gm = rowBase + tr * TM + i;
        if (gm < M) {
            if (OUT_HALF) {
                __half* Ch = (__half*)Cv;
                uint4 o;
                unsigned int* op = (unsigned int*)&o;
                #pragma unroll
                for (int j = 0; j < TN / 2; j++) {
                    F4U2 t; t.u[0] = acc2[i][j];
                    __half2 h = __float22half2_rn(make_float2(t.s[0], t.s[1]));
                    op[j] = *(unsigned int*)&h;
                }
                *(uint4*)(Ch + (size_t)gm * N + colBase + tc * TN) = o;
            } else {
                float* C = (float*)Cv;
                #pragma unroll
                for (int j = 0; j < TN / 2; j += 2) {
                    F4U2 o;
                    o.u[0] = acc2[i][j];
                    o.u[1] = acc2[i][j + 1];
                    *(float4*)(C + (size_t)gm * N + colBase + tc * TN + 2 * j) = o.f;
                }
            }
        }
    }
}

// ---------------------------------------------------------------------------
// SpMM (CSR, warp-per-row), fp16 gather / fp32 accumulate
// ---------------------------------------------------------------------------
__global__ void __launch_bounds__(256)
spmm128_relu_kernel(const __half2* __restrict__ src,   // [N, 64] half2
                    const float* __restrict__ bias,
                    float* __restrict__ dst) {
    int row = blockIdx.x * 8 + threadIdx.y;
    if (row >= N_NODES) return;
    const int lane = threadIdx.x;
    const int s = g_row_start[row];
    const int e = g_row_start[row + 1];

    float4 acc = make_float4(0.f, 0.f, 0.f, 0.f);
    int j = s;
    for (; j + 32 <= e; j += 32) {
        unsigned long long pe = g_edge[j + lane];
        int   c = (int)(unsigned int)pe;
        float v = __uint_as_float((unsigned int)(pe >> 32));
        #pragma unroll
        for (int t = 0; t < 32; t++) {
            int   cc = __shfl_sync(0xffffffffu, c, t);
            float vv = __shfl_sync(0xffffffffu, v, t);
            // lane covers features [4*lane, 4*lane+4): 2 half2 = 8B
            const __half2* p = src + (size_t)cc * (F1 / 2) + lane * 2;
            uint2 raw = *(const uint2*)p;
            float2 f0 = __half22float2(*(const __half2*)&raw.x);
            float2 f1 = __half22float2(*(const __half2*)&raw.y);
            acc.x = fmaf(vv, f0.x, acc.x);
            acc.y = fmaf(vv, f0.y, acc.y);
            acc.z = fmaf(vv, f1.x, acc.z);
            acc.w = fmaf(vv, f1.y, acc.w);
        }
    }
    if (j < e) {
        int myj = j + lane;
        unsigned long long pe = (myj < e) ? g_edge[myj] : 0ull;
        int   c = (int)(unsigned int)pe;
        float v = __uint_as_float((unsigned int)(pe >> 32));
        int cnt = e - j;
        for (int t = 0; t < cnt; t++) {
            int   cc = __shfl_sync(0xffffffffu, c, t);
            float vv = __shfl_sync(0xffffffffu, v, t);
            const __half2* p = src + (size_t)cc * (F1 / 2) + lane * 2;
            uint2 raw = *(const uint2*)p;
            float2 f0 = __half22float2(*(const __half2*)&raw.x);
            float2 f1 = __half22float2(*(const __half2*)&raw.y);
            acc.x = fmaf(vv, f0.x, acc.x);
            acc.y = fmaf(vv, f0.y, acc.y);
            acc.z = fmaf(vv, f1.x, acc.z);
            acc.w = fmaf(vv, f1.y, acc.w);
        }
    }
    float4 b = *(const float4*)(bias + lane * 4);
    float4 o;
    o.x = fmaxf(acc.x + b.x, 0.f);
    o.y = fmaxf(acc.y + b.y, 0.f);
    o.z = fmaxf(acc.z + b.z, 0.f);
    o.w = fmaxf(acc.w + b.w, 0.f);
    *(float4*)(dst + (size_t)row * F1 + lane * 4) = o;
}

__global__ void __launch_bounds__(256)
spmm64_bias_kernel(const __half2* __restrict__ src,   // [N, 32] half2
                   const float* __restrict__ bias,
                   float* __restrict__ dst) {
    int row = blockIdx.x * 8 + threadIdx.y;
    if (row >= N_NODES) return;
    const int lane = threadIdx.x;
    const int s = g_row_start[row];
    const int e = g_row_start[row + 1];

    float2 acc = make_float2(0.f, 0.f);
    int j = s;
    for (; j + 32 <= e; j += 32) {
        unsigned long long pe = g_edge[j + lane];
        int   c = (int)(unsigned int)pe;
        float v = __uint_as_float((unsigned int)(pe >> 32));
        #pragma unroll
        for (int t = 0; t < 32; t++) {
            int   cc = __shfl_sync(0xffffffffu, c, t);
            float vv = __shfl_sync(0xffffffffu, v, t);
            float2 f = __half22float2(src[(size_t)cc * (F2 / 2) + lane]);
            acc.x = fmaf(vv, f.x, acc.x);
            acc.y = fmaf(vv, f.y, acc.y);
        }
    }
    if (j < e) {
        int myj = j + lane;
        unsigned long long pe = (myj < e) ? g_edge[myj] : 0ull;
        int   c = (int)(unsigned int)pe;
        float v = __uint_as_float((unsigned int)(pe >> 32));
        int cnt = e - j;
        for (int t = 0; t < cnt; t++) {
            int   cc = __shfl_sync(0xffffffffu, c, t);
            float vv = __shfl_sync(0xffffffffu, v, t);
            float2 f = __half22float2(src[(size_t)cc * (F2 / 2) + lane]);
            acc.x = fmaf(vv, f.x, acc.x);
            acc.y = fmaf(vv, f.y, acc.y);
        }
    }
    float2 b = *(const float2*)(bias + lane * 2);
    float2 o;
    o.x = acc.x + b.x;
    o.y = acc.y + b.y;
    *(float2*)(dst + (size_t)row * F2 + lane * 2) = o;
}

// ---------------------------------------------------------------------------
// Launch
// ---------------------------------------------------------------------------
extern "C" void kernel_launch(void* const* d_in, const int* in_sizes, int n_in,
                              void* d_out, int out_size) {
    const float* x    = (const float*)d_in[0];
    const int*   rows = (const int*)d_in[1];
    const int*   cols = (const int*)d_in[2];
    const float* vals = (const float*)d_in[3];
    const float* W1   = (const float*)d_in[4];
    const float* b1   = (const float*)d_in[5];
    const float* W2   = (const float*)d_in[6];
    const float* b2   = (const float*)d_in[7];
    float* out = (float*)d_out;

    void *yp, *h1p, *zp;
    cudaGetSymbolAddress(&yp,  g_y);
    cudaGetSymbolAddress(&h1p, g_h1);
    cudaGetSymbolAddress(&zp,  g_z);
    __half2* y  = (__half2*)yp;
    float*   h1 = (float*)h1p;
    __half2* z  = (__half2*)zp;

    // CSR build
    zero_cnt_kernel<<<400, 256>>>();
    hist_kernel<<<(N_EDGES + 255) / 256, 256>>>(rows);
    scan1_kernel<<<N_CHUNKS, 1024>>>();
    scan2_kernel<<<1, 128>>>();
    scan3_kernel<<<N_CHUNKS, 1024>>>();
    scatter_kernel<<<(N_EDGES + 255) / 256, 256>>>(rows, cols, vals);

    // y = fp16(x @ W1)   [100000,256] x [256,128]
    {
        dim3 grid(F1 / 128, (N_NODES + 127) / 128);
        sgemm_kernel<128, 128, 16, 8, 8, true><<<grid, 256>>>(x, W1, y,
                                                              N_NODES, F0, F1);
    }
    // h1 = relu(A y + b1)  (fp32)
    spmm128_relu_kernel<<<(N_NODES + 7) / 8, dim3(32, 8)>>>(y, b1, h1);

    // z = fp16(h1 @ W2)  [100000,128] x [128,64]
    {
        dim3 grid(F2 / 64, (N_NODES + 127) / 128);
        sgemm_kernel<128, 64, 16, 8, 8, true><<<grid, 128>>>(h1, W2, z,
                                                             N_NODES, F1, F2);
    }
    // out = A z + b2
    spmm64_bias_kernel<<<(N_NODES + 7) / 8, dim3(32, 8)>>>(z, b2, out);
}